// round 1
// baseline (speedup 1.0000x reference)
#include <cuda_runtime.h>
#include <cstdint>

#define BN_EPS 1e-5f

constexpr int B_   = 32;
constexpr int P_   = 512;
constexpr int N_   = 32;   // points per polyline
constexpr int C_   = 9;    // input channels
constexpr int H_   = 64;   // hidden
constexpr int OUT_ = 128;
constexpr int NPOLY = B_ * P_;   // 16384

// -------- device scratch (no allocations allowed) --------
__device__ float g_Wpre[C_ * H_];     // BN-folded pre weights [c][h]
__device__ float g_b0v[H_];
__device__ float g_W1[2 * H_ * H_];   // BN-folded W1 [k][h], k in [0,128)
__device__ float g_b1v[H_];
__device__ float g_W2[H_ * H_];       // BN-folded W2 [k][h]
__device__ float g_b2v[H_];
__device__ int   g_mask4;             // 1 if mask elements are 4 bytes wide

// ============================================================
// Fold BN into linear weights + detect mask element width.
// ============================================================
__global__ void fold_kernel(const float* __restrict__ Wpre,
                            const float* __restrict__ g0,  const float* __restrict__ b0,
                            const float* __restrict__ m0,  const float* __restrict__ v0,
                            const float* __restrict__ W1,
                            const float* __restrict__ g1,  const float* __restrict__ bb1,
                            const float* __restrict__ m1,  const float* __restrict__ v1,
                            const float* __restrict__ W2,
                            const float* __restrict__ g2,  const float* __restrict__ bb2,
                            const float* __restrict__ m2,  const float* __restrict__ v2,
                            const void*  __restrict__ mask)
{
    __shared__ float s0[H_], s1[H_], s2[H_];
    int tid = threadIdx.x;
    if (tid < H_) {
        s0[tid] = g0[tid] * rsqrtf(v0[tid] + BN_EPS);
        s1[tid] = g1[tid] * rsqrtf(v1[tid] + BN_EPS);
        s2[tid] = g2[tid] * rsqrtf(v2[tid] + BN_EPS);
    }
    __syncthreads();

    for (int i = tid; i < C_ * H_;     i += blockDim.x) g_Wpre[i] = Wpre[i] * s0[i % H_];
    for (int i = tid; i < 2 * H_ * H_; i += blockDim.x) g_W1[i]   = W1[i]   * s1[i % H_];
    for (int i = tid; i < H_ * H_;     i += blockDim.x) g_W2[i]   = W2[i]   * s2[i % H_];

    if (tid < H_) {
        g_b0v[tid] = b0[tid]  - m0[tid] * s0[tid];
        g_b1v[tid] = bb1[tid] - m1[tid] * s1[tid];
        g_b2v[tid] = bb2[tid] - m2[tid] * s2[tid];
    }

    // Mask dtype sniffing. bool -> 1 byte per element, values {0,1}.
    // float32 1.0f has bytes {00,00,80,3F}; int32 1 has bytes {01,00,00,00}.
    // Rule: any byte > 1  -> 4-byte elements (float).
    //       all bytes at i%4!=0 are 0 AND some byte at i%4==0 is 1 -> 4-byte (int 0/1).
    //       otherwise -> 1-byte bool.
    if (tid == 0) {
        const unsigned char* mb = (const unsigned char*)mask;
        unsigned mx = 0, off = 0, al = 0;
        #pragma unroll 4
        for (int i = 0; i < 4096; i++) {
            unsigned v = mb[i];
            mx |= v;
            if ((i & 3) != 0) off |= v; else al |= v;
        }
        g_mask4 = (mx > 1u) || (off == 0u && al != 0u);
    }
}

// ============================================================
// Fused PointNet polyline encoder: one CTA per polyline,
// 64 threads, thread h owns hidden channel h.
// ============================================================
__global__ __launch_bounds__(64) void pnet_kernel(
    const float* __restrict__ poly,   // [NPOLY, N, C]
    const void*  __restrict__ mask,   // [NPOLY, N]
    const float* __restrict__ W3,     // [H, H]
    const float* __restrict__ b3,     // [H]
    const float* __restrict__ W4,     // [H, OUT]
    const float* __restrict__ b4,     // [OUT]
    float*       __restrict__ out)    // [NPOLY, OUT]
{
    __shared__ float sP[N_ * C_];
    __shared__ float sM[N_];
    __shared__ float sX0[N_ * H_];
    __shared__ float sX1[N_ * H_];
    __shared__ float sPool[H_];
    __shared__ float sH4[H_];
    __shared__ int   sValid;

    const int h   = threadIdx.x;
    const int pid = blockIdx.x;

    // ---- load points + mask ----
    const float* pp = poly + (size_t)pid * (N_ * C_);
    for (int i = h; i < N_ * C_; i += 64) sP[i] = pp[i];
    if (h < N_) {
        bool valid;
        size_t idx = (size_t)pid * N_ + h;
        if (g_mask4) valid = (((const unsigned*)mask)[idx] != 0u);
        else         valid = (((const unsigned char*)mask)[idx] != 0u);
        sM[h] = valid ? 1.0f : 0.0f;
    }
    if (h == 0) sValid = 0;
    __syncthreads();
    if (h < N_ && sM[h] != 0.0f) sValid = 1;   // benign: all writers store 1

    // ---- stage 1: X0 = relu(BN(P @ Wpre)) * mask ; pooled1 = max_n ----
    float w9[C_];
    #pragma unroll
    for (int c = 0; c < C_; c++) w9[c] = g_Wpre[c * H_ + h];
    {
        const float bb = g_b0v[h];
        float pm = 0.0f;
        #pragma unroll
        for (int n = 0; n < N_; n++) {
            float a = bb;
            #pragma unroll
            for (int c = 0; c < C_; c++) a = fmaf(sP[n * C_ + c], w9[c], a);
            a = fmaxf(a, 0.0f) * sM[n];
            sX0[n * H_ + h] = a;
            pm = fmaxf(pm, a);
        }
        sPool[h] = pm;
    }
    __syncthreads();

    float acc[N_];

    // ---- stage 2: X1 = relu(BN(concat(X0, pooled1) @ W1)) * mask ----
    {
        // pooled half contributes the same scalar to every row n
        float tp = g_b1v[h];
        #pragma unroll
        for (int k = 0; k < H_; k++) tp = fmaf(sPool[k], g_W1[(H_ + k) * H_ + h], tp);
        #pragma unroll
        for (int n = 0; n < N_; n++) acc[n] = tp;

        #pragma unroll 1
        for (int k0 = 0; k0 < H_; k0 += 8) {
            float w[8];
            #pragma unroll
            for (int j = 0; j < 8; j++) w[j] = g_W1[(k0 + j) * H_ + h];
            #pragma unroll
            for (int n = 0; n < N_; n++) {
                float4 xa = *(const float4*)&sX0[n * H_ + k0];
                float4 xb = *(const float4*)&sX0[n * H_ + k0 + 4];
                float a = acc[n];
                a = fmaf(xa.x, w[0], a); a = fmaf(xa.y, w[1], a);
                a = fmaf(xa.z, w[2], a); a = fmaf(xa.w, w[3], a);
                a = fmaf(xb.x, w[4], a); a = fmaf(xb.y, w[5], a);
                a = fmaf(xb.z, w[6], a); a = fmaf(xb.w, w[7], a);
                acc[n] = a;
            }
        }
        #pragma unroll
        for (int n = 0; n < N_; n++) sX1[n * H_ + h] = fmaxf(acc[n], 0.0f) * sM[n];
    }
    __syncthreads();

    // ---- stage 3: X2 = relu(BN(X1 @ W2)) * mask ; pooled3 = max_n ----
    {
        const float bb = g_b2v[h];
        #pragma unroll
        for (int n = 0; n < N_; n++) acc[n] = bb;

        #pragma unroll 1
        for (int k0 = 0; k0 < H_; k0 += 8) {
            float w[8];
            #pragma unroll
            for (int j = 0; j < 8; j++) w[j] = g_W2[(k0 + j) * H_ + h];
            #pragma unroll
            for (int n = 0; n < N_; n++) {
                float4 xa = *(const float4*)&sX1[n * H_ + k0];
                float4 xb = *(const float4*)&sX1[n * H_ + k0 + 4];
                float a = acc[n];
                a = fmaf(xa.x, w[0], a); a = fmaf(xa.y, w[1], a);
                a = fmaf(xa.z, w[2], a); a = fmaf(xa.w, w[3], a);
                a = fmaf(xb.x, w[4], a); a = fmaf(xb.y, w[5], a);
                a = fmaf(xb.z, w[6], a); a = fmaf(xb.w, w[7], a);
                acc[n] = a;
            }
        }
        float pm = 0.0f;
        #pragma unroll
        for (int n = 0; n < N_; n++) pm = fmaxf(pm, fmaxf(acc[n], 0.0f) * sM[n]);
        sPool[h] = pm;   // all prior sPool reads completed before last barrier
    }
    __syncthreads();

    // ---- head: out = (relu(pooled3 @ W3 + b3) @ W4 + b4) * anyvalid ----
    {
        float a3 = b3[h];
        #pragma unroll
        for (int k = 0; k < H_; k++) a3 = fmaf(sPool[k], W3[k * H_ + h], a3);
        sH4[h] = fmaxf(a3, 0.0f);
    }
    __syncthreads();

    const float vf = sValid ? 1.0f : 0.0f;
    float* op = out + (size_t)pid * OUT_;
    #pragma unroll
    for (int r = 0; r < 2; r++) {
        const int o = h + r * H_;
        float a = b4[o];
        #pragma unroll
        for (int k = 0; k < H_; k++) a = fmaf(sH4[k], W4[k * OUT_ + o], a);
        op[o] = a * vf;
    }
}

// ============================================================
// Launch
// ============================================================
extern "C" void kernel_launch(void* const* d_in, const int* in_sizes, int n_in,
                              void* d_out, int out_size)
{
    const float* poly = (const float*)d_in[0];
    const float* Wpre = (const float*)d_in[1];
    const float* g0   = (const float*)d_in[2];
    const float* b0   = (const float*)d_in[3];
    const float* m0   = (const float*)d_in[4];
    const float* v0   = (const float*)d_in[5];
    const float* W1   = (const float*)d_in[6];
    const float* g1   = (const float*)d_in[7];
    const float* bb1  = (const float*)d_in[8];
    const float* m1   = (const float*)d_in[9];
    const float* v1   = (const float*)d_in[10];
    const float* W2   = (const float*)d_in[11];
    const float* g2   = (const float*)d_in[12];
    const float* bb2  = (const float*)d_in[13];
    const float* m2   = (const float*)d_in[14];
    const float* v2   = (const float*)d_in[15];
    const float* W3   = (const float*)d_in[16];
    const float* b3   = (const float*)d_in[17];
    const float* W4   = (const float*)d_in[18];
    const float* b4   = (const float*)d_in[19];
    const void*  mask = d_in[20];

    fold_kernel<<<1, 256>>>(Wpre, g0, b0, m0, v0,
                            W1, g1, bb1, m1, v1,
                            W2, g2, bb2, m2, v2, mask);
    pnet_kernel<<<NPOLY, 64>>>(poly, mask, W3, b3, W4, b4, (float*)d_out);
}

// round 2
// speedup vs baseline: 2.7275x; 2.7275x over previous
#include <cuda_runtime.h>
#include <cstdint>

#define BN_EPS 1e-5f

constexpr int N_    = 32;   // points per polyline
constexpr int C_    = 9;    // input channels
constexpr int H_    = 64;   // hidden
constexpr int OUT_  = 128;
constexpr int SAW   = 68;   // smem X row stride (words) -> conflict-free frags

// -------- device scratch (no allocations allowed) --------
__device__ float    g_Wpre[C_ * H_];      // BN-folded pre weights [c][h]
__device__ float    g_b0v[H_];
__device__ float    g_W1hi[H_ * H_];      // folded W1 rows 64..127 (pooled half), [k][h]
__device__ float    g_b1v[H_];
__device__ float    g_b2v[H_];
__device__ uint32_t g_W1f[4096];          // W1 low half, tf32 B-fragment layout
__device__ uint32_t g_W2f[4096];          // W2, tf32 B-fragment layout
__device__ int      g_mask4;              // 1 if mask elements are 4 bytes wide

__device__ __forceinline__ uint32_t f2tf32(float x) {
    uint32_t r;
    asm("cvt.rna.tf32.f32 %0, %1;" : "=r"(r) : "f"(x));
    return r;
}

__device__ __forceinline__ void mma_tf32(float& c0, float& c1, float& c2, float& c3,
                                         uint32_t a0, uint32_t a1, uint32_t a2, uint32_t a3,
                                         uint32_t b0, uint32_t b1) {
    asm volatile(
        "mma.sync.aligned.m16n8k8.row.col.f32.tf32.tf32.f32 "
        "{%0,%1,%2,%3},{%4,%5,%6,%7},{%8,%9},{%0,%1,%2,%3};\n"
        : "+f"(c0), "+f"(c1), "+f"(c2), "+f"(c3)
        : "r"(a0), "r"(a1), "r"(a2), "r"(a3), "r"(b0), "r"(b1));
}

// ============================================================
// Fold BN into weights, build tf32 B-fragment tables, sniff mask dtype.
// ============================================================
__global__ void fold_kernel(const float* __restrict__ Wpre,
                            const float* __restrict__ g0,  const float* __restrict__ b0,
                            const float* __restrict__ m0,  const float* __restrict__ v0,
                            const float* __restrict__ W1,
                            const float* __restrict__ g1,  const float* __restrict__ bb1,
                            const float* __restrict__ m1,  const float* __restrict__ v1,
                            const float* __restrict__ W2,
                            const float* __restrict__ g2,  const float* __restrict__ bb2,
                            const float* __restrict__ m2,  const float* __restrict__ v2,
                            const void*  __restrict__ mask)
{
    __shared__ float s0[H_], s1[H_], s2[H_];
    __shared__ unsigned red[3];   // mx, off, al
    const int tid = threadIdx.x;

    if (tid < 3) red[tid] = 0u;
    if (tid < H_) {
        float sc0 = g0[tid] * rsqrtf(v0[tid] + BN_EPS);
        float sc1 = g1[tid] * rsqrtf(v1[tid] + BN_EPS);
        float sc2 = g2[tid] * rsqrtf(v2[tid] + BN_EPS);
        s0[tid] = sc0; s1[tid] = sc1; s2[tid] = sc2;
        g_b0v[tid] = b0[tid]  - m0[tid] * sc0;
        g_b1v[tid] = bb1[tid] - m1[tid] * sc1;
        g_b2v[tid] = bb2[tid] - m2[tid] * sc2;
    }
    __syncthreads();

    for (int i = tid; i < C_ * H_; i += blockDim.x)
        g_Wpre[i] = Wpre[i] * s0[i & 63];

    for (int i = tid; i < H_ * H_; i += blockDim.x) {
        int k = i >> 6, h = i & 63;
        g_W1hi[i] = W1[(H_ + k) * H_ + h] * s1[h];
    }

    // B-fragment layout for mma.sync.m16n8k8.row.col (tf32):
    // idx = (((w*8 + kt)*4 + t)*32 + lane)*2 + r
    // value = W[k][h] with k = kt*8 + (lane&3) + r*4, h = w*32 + t*8 + (lane>>2)
    for (int i = tid; i < 4096; i += blockDim.x) {
        int r    = i & 1;
        int lane = (i >> 1) & 31;
        int t    = (i >> 6) & 3;
        int kt   = (i >> 8) & 7;
        int w    = (i >> 11) & 1;
        int k = kt * 8 + (lane & 3) + r * 4;
        int h = w * 32 + t * 8 + (lane >> 2);
        g_W1f[i] = f2tf32(W1[k * H_ + h] * s1[h]);
        g_W2f[i] = f2tf32(W2[k * H_ + h] * s2[h]);
    }

    // Parallel mask dtype sniff over first 1024 bytes.
    {
        const unsigned char* mb = (const unsigned char*)mask;
        unsigned mx = 0, off = 0, al = 0;
        for (int i = tid * 4; i < tid * 4 + 4; i++) {
            unsigned v = mb[i];
            mx |= v;
            if ((i & 3) != 0) off |= v; else al |= v;
        }
        atomicOr(&red[0], mx);
        atomicOr(&red[1], off);
        atomicOr(&red[2], al);
        __syncthreads();
        if (tid == 0)
            g_mask4 = (red[0] > 1u) || (red[1] == 0u && red[2] != 0u);
    }
}

// ============================================================
// Fused PointNet polyline encoder, tf32 tensor-core stages.
// One CTA (64 threads = 2 warps) per polyline. Warp w owns h in [32w, 32w+32).
// ============================================================
__global__ __launch_bounds__(64) void pnet_kernel(
    const float* __restrict__ poly,   // [NPOLY, N, C]
    const void*  __restrict__ mask,   // [NPOLY, N]
    const float* __restrict__ W3,     // [H, H]
    const float* __restrict__ b3,     // [H]
    const float* __restrict__ W4,     // [H, OUT]
    const float* __restrict__ b4,     // [OUT]
    float*       __restrict__ out)    // [NPOLY, OUT]
{
    __shared__ __align__(16) uint32_t sA[N_ * SAW];  // X0 / X1 (tf32), X2 (f32)
    __shared__ __align__(16) float sP[N_ * C_];
    __shared__ float sM[N_];
    __shared__ float sPool[H_];
    __shared__ float sT[H_];
    __shared__ float sH4[H_];
    __shared__ int   sValid;

    const int h    = threadIdx.x;
    const int lane = h & 31;
    const int w    = h >> 5;
    const int pid  = blockIdx.x;

    // ---- load points + mask ----
    {
        const float4* pp4 = (const float4*)(poly + (size_t)pid * (N_ * C_));
        for (int i = h; i < (N_ * C_) / 4; i += 64) ((float4*)sP)[i] = pp4[i];
    }
    if (h < N_) {
        bool valid;
        size_t idx = (size_t)pid * N_ + h;
        if (g_mask4) valid = (((const unsigned*)mask)[idx] != 0u);
        else         valid = (((const unsigned char*)mask)[idx] != 0u);
        sM[h] = valid ? 1.0f : 0.0f;
    }
    if (h == 0) sValid = 0;
    __syncthreads();
    if (h < N_ && sM[h] != 0.0f) sValid = 1;   // benign race: all writers store 1

    // ---- stage 1 (scalar, K=9): X0 = relu(BN(P@Wpre))*mask ; pooled1 ----
    {
        float w9[C_];
        #pragma unroll
        for (int c = 0; c < C_; c++) w9[c] = g_Wpre[c * H_ + h];
        const float bb = g_b0v[h];
        float pm = 0.0f;
        #pragma unroll
        for (int n = 0; n < N_; n++) {
            float a = bb;
            #pragma unroll
            for (int c = 0; c < C_; c++) a = fmaf(sP[n * C_ + c], w9[c], a);
            a = fmaxf(a, 0.0f) * sM[n];
            pm = fmaxf(pm, a);
            sA[n * SAW + h] = f2tf32(a);
        }
        sPool[h] = pm;
    }
    __syncthreads();

    // ---- per-polyline bias: t[h] = b1' + pooled1 @ W1_hi ----
    {
        float tp = g_b1v[h];
        #pragma unroll
        for (int k = 0; k < H_; k++) tp = fmaf(sPool[k], g_W1hi[k * H_ + h], tp);
        sT[h] = tp;
    }
    __syncthreads();

    float acc[2][4][4];

    // ================= stage 2: X1 = relu(X0 @ W1_lo + t) * mask =================
    {
        #pragma unroll
        for (int t = 0; t < 4; t++) {
            int hc = w * 32 + t * 8 + (lane & 3) * 2;
            float v0 = sT[hc], v1 = sT[hc + 1];
            #pragma unroll
            for (int m = 0; m < 2; m++) {
                acc[m][t][0] = v0; acc[m][t][1] = v1;
                acc[m][t][2] = v0; acc[m][t][3] = v1;
            }
        }
        const uint32_t* Wf = g_W1f + w * 2048;
        const int r0 = lane >> 2, c0 = lane & 3;
        #pragma unroll
        for (int kt = 0; kt < 8; kt++) {
            uint32_t a[2][4];
            #pragma unroll
            for (int m = 0; m < 2; m++) {
                int base = (m * 16 + r0) * SAW + kt * 8 + c0;
                a[m][0] = sA[base];
                a[m][1] = sA[base + 8 * SAW];
                a[m][2] = sA[base + 4];
                a[m][3] = sA[base + 8 * SAW + 4];
            }
            #pragma unroll
            for (int t = 0; t < 4; t++) {
                uint2 b = *(const uint2*)(Wf + ((kt * 4 + t) * 32 + lane) * 2);
                #pragma unroll
                for (int m = 0; m < 2; m++)
                    mma_tf32(acc[m][t][0], acc[m][t][1], acc[m][t][2], acc[m][t][3],
                             a[m][0], a[m][1], a[m][2], a[m][3], b.x, b.y);
            }
        }
    }
    __syncthreads();   // all reads of X0 complete
    {
        const int g = lane >> 2;
        #pragma unroll
        for (int m = 0; m < 2; m++) {
            float rm0 = sM[m * 16 + g], rm1 = sM[m * 16 + g + 8];
            #pragma unroll
            for (int t = 0; t < 4; t++) {
                int hc = w * 32 + t * 8 + (lane & 3) * 2;
                int nb = (m * 16 + g) * SAW;
                sA[nb + hc]               = f2tf32(fmaxf(acc[m][t][0], 0.0f) * rm0);
                sA[nb + hc + 1]           = f2tf32(fmaxf(acc[m][t][1], 0.0f) * rm0);
                sA[nb + 8 * SAW + hc]     = f2tf32(fmaxf(acc[m][t][2], 0.0f) * rm1);
                sA[nb + 8 * SAW + hc + 1] = f2tf32(fmaxf(acc[m][t][3], 0.0f) * rm1);
            }
        }
    }
    __syncthreads();

    // ================= stage 3: X2 = relu(X1 @ W2 + b2') * mask =================
    {
        #pragma unroll
        for (int t = 0; t < 4; t++) {
            int hc = w * 32 + t * 8 + (lane & 3) * 2;
            float v0 = g_b2v[hc], v1 = g_b2v[hc + 1];
            #pragma unroll
            for (int m = 0; m < 2; m++) {
                acc[m][t][0] = v0; acc[m][t][1] = v1;
                acc[m][t][2] = v0; acc[m][t][3] = v1;
            }
        }
        const uint32_t* Wf = g_W2f + w * 2048;
        const int r0 = lane >> 2, c0 = lane & 3;
        #pragma unroll
        for (int kt = 0; kt < 8; kt++) {
            uint32_t a[2][4];
            #pragma unroll
            for (int m = 0; m < 2; m++) {
                int base = (m * 16 + r0) * SAW + kt * 8 + c0;
                a[m][0] = sA[base];
                a[m][1] = sA[base + 8 * SAW];
                a[m][2] = sA[base + 4];
                a[m][3] = sA[base + 8 * SAW + 4];
            }
            #pragma unroll
            for (int t = 0; t < 4; t++) {
                uint2 b = *(const uint2*)(Wf + ((kt * 4 + t) * 32 + lane) * 2);
                #pragma unroll
                for (int m = 0; m < 2; m++)
                    mma_tf32(acc[m][t][0], acc[m][t][1], acc[m][t][2], acc[m][t][3],
                             a[m][0], a[m][1], a[m][2], a[m][3], b.x, b.y);
            }
        }
    }
    __syncthreads();   // all reads of X1 complete
    {
        float* sX2 = (float*)sA;
        const int g = lane >> 2;
        #pragma unroll
        for (int m = 0; m < 2; m++) {
            float rm0 = sM[m * 16 + g], rm1 = sM[m * 16 + g + 8];
            #pragma unroll
            for (int t = 0; t < 4; t++) {
                int hc = w * 32 + t * 8 + (lane & 3) * 2;
                int nb = (m * 16 + g) * SAW;
                sX2[nb + hc]               = fmaxf(acc[m][t][0], 0.0f) * rm0;
                sX2[nb + hc + 1]           = fmaxf(acc[m][t][1], 0.0f) * rm0;
                sX2[nb + 8 * SAW + hc]     = fmaxf(acc[m][t][2], 0.0f) * rm1;
                sX2[nb + 8 * SAW + hc + 1] = fmaxf(acc[m][t][3], 0.0f) * rm1;
            }
        }
    }
    __syncthreads();

    // ---- pool over n ----
    {
        const float* sX2 = (const float*)sA;
        float pm = 0.0f;
        #pragma unroll
        for (int n = 0; n < N_; n++) pm = fmaxf(pm, sX2[n * SAW + h]);
        sPool[h] = pm;
    }
    __syncthreads();

    // ---- head: out = (relu(pooled3 @ W3 + b3) @ W4 + b4) * anyvalid ----
    {
        float a3 = b3[h];
        #pragma unroll
        for (int k = 0; k < H_; k++) a3 = fmaf(sPool[k], W3[k * H_ + h], a3);
        sH4[h] = fmaxf(a3, 0.0f);
    }
    __syncthreads();

    const float vf = sValid ? 1.0f : 0.0f;
    float* op = out + (size_t)pid * OUT_;
    #pragma unroll
    for (int r = 0; r < 2; r++) {
        const int o = h + r * H_;
        float a = b4[o];
        #pragma unroll
        for (int k = 0; k < H_; k++) a = fmaf(sH4[k], W4[k * OUT_ + o], a);
        op[o] = a * vf;
    }
}

// ============================================================
// Launch
// ============================================================
extern "C" void kernel_launch(void* const* d_in, const int* in_sizes, int n_in,
                              void* d_out, int out_size)
{
    const float* poly = (const float*)d_in[0];
    const float* Wpre = (const float*)d_in[1];
    const float* g0   = (const float*)d_in[2];
    const float* b0   = (const float*)d_in[3];
    const float* m0   = (const float*)d_in[4];
    const float* v0   = (const float*)d_in[5];
    const float* W1   = (const float*)d_in[6];
    const float* g1   = (const float*)d_in[7];
    const float* bb1  = (const float*)d_in[8];
    const float* m1   = (const float*)d_in[9];
    const float* v1   = (const float*)d_in[10];
    const float* W2   = (const float*)d_in[11];
    const float* g2   = (const float*)d_in[12];
    const float* bb2  = (const float*)d_in[13];
    const float* m2   = (const float*)d_in[14];
    const float* v2   = (const float*)d_in[15];
    const float* W3   = (const float*)d_in[16];
    const float* b3   = (const float*)d_in[17];
    const float* W4   = (const float*)d_in[18];
    const float* b4   = (const float*)d_in[19];
    const void*  mask = d_in[20];

    const int npoly = in_sizes[0] / (N_ * C_);

    fold_kernel<<<1, 256>>>(Wpre, g0, b0, m0, v0,
                            W1, g1, bb1, m1, v1,
                            W2, g2, bb2, m2, v2, mask);
    pnet_kernel<<<npoly, 64>>>(poly, mask, W3, b3, W4, b4, (float*)d_out);
}

// round 4
// speedup vs baseline: 3.1876x; 1.1687x over previous
#include <cuda_runtime.h>
#include <cstdint>

#define BN_EPS 1e-5f

constexpr int N_    = 32;   // points per polyline
constexpr int C_    = 9;    // input channels
constexpr int H_    = 64;   // hidden
constexpr int OUT_  = 128;
constexpr int SAW   = 68;   // X tile row stride (words): >=64 data + pad, conflict-free frags
constexpr int SPW   = 12;   // padded input row stride (words): >=9 data, conflict-free
constexpr int SVW   = 68;   // stride for [4][64] vector mats

// -------- device scratch (no allocations allowed) --------
__device__ float    g_b0v[H_], g_b1v[H_], g_b2v[H_];
__device__ float    g_Wpre8[H_];        // folded Wpre row k=8 (residual)
__device__ uint32_t g_W0f[512];         // folded Wpre k=0..7, B-frag layout
__device__ uint32_t g_W1f[4096];        // folded W1 low half  (k=0..63)
__device__ uint32_t g_W1hf[4096];       // folded W1 high half (k=64..127)
__device__ uint32_t g_W2f[4096];        // folded W2
__device__ uint32_t g_W3f[4096];        // raw W3
__device__ uint32_t g_W4f[8192];        // raw W4 [64][128]
__device__ int      g_mask4;            // 1 if mask elements are 4 bytes wide

__device__ __forceinline__ uint32_t f2tf32(float x) {
    uint32_t r;
    asm("cvt.rna.tf32.f32 %0, %1;" : "=r"(r) : "f"(x));
    return r;
}

__device__ __forceinline__ void mma_tf32(float& c0, float& c1, float& c2, float& c3,
                                         uint32_t a0, uint32_t a1, uint32_t a2, uint32_t a3,
                                         uint32_t b0, uint32_t b1) {
    asm volatile(
        "mma.sync.aligned.m16n8k8.row.col.f32.tf32.tf32.f32 "
        "{%0,%1,%2,%3},{%4,%5,%6,%7},{%8,%9},{%0,%1,%2,%3};\n"
        : "+f"(c0), "+f"(c1), "+f"(c2), "+f"(c3)
        : "r"(a0), "r"(a1), "r"(a2), "r"(a3), "r"(b0), "r"(b1));
}

// ============================================================
// Fold BN into weights, build tf32 B-fragment tables, sniff mask dtype.
// ============================================================
__global__ void fold_kernel(const float* __restrict__ Wpre,
                            const float* __restrict__ g0,  const float* __restrict__ b0,
                            const float* __restrict__ m0,  const float* __restrict__ v0,
                            const float* __restrict__ W1,
                            const float* __restrict__ g1,  const float* __restrict__ bb1,
                            const float* __restrict__ m1,  const float* __restrict__ v1,
                            const float* __restrict__ W2,
                            const float* __restrict__ g2,  const float* __restrict__ bb2,
                            const float* __restrict__ m2,  const float* __restrict__ v2,
                            const float* __restrict__ W3,
                            const float* __restrict__ W4,
                            const void*  __restrict__ mask)
{
    __shared__ float s0[H_], s1[H_], s2[H_];
    __shared__ unsigned red[3];
    const int tid = threadIdx.x;

    if (tid < 3) red[tid] = 0u;
    if (tid < H_) {
        float sc0 = g0[tid] * rsqrtf(v0[tid] + BN_EPS);
        float sc1 = g1[tid] * rsqrtf(v1[tid] + BN_EPS);
        float sc2 = g2[tid] * rsqrtf(v2[tid] + BN_EPS);
        s0[tid] = sc0; s1[tid] = sc1; s2[tid] = sc2;
        g_b0v[tid] = b0[tid]  - m0[tid] * sc0;
        g_b1v[tid] = bb1[tid] - m1[tid] * sc1;
        g_b2v[tid] = bb2[tid] - m2[tid] * sc2;
        g_Wpre8[tid] = Wpre[8 * H_ + tid] * sc0;
    }
    __syncthreads();

    // B-fragment layout for mma.sync.m16n8k8.row.col (tf32):
    // value = W[k][h], k = kt*8 + (lane&3) + r*4, h = w*32 + t*8 + (lane>>2)

    // Wpre (single k-step, k=0..7)
    for (int i = tid; i < 512; i += blockDim.x) {
        int r = i & 1, lane = (i >> 1) & 31, t = (i >> 6) & 3, w = (i >> 8) & 1;
        int k = (lane & 3) + r * 4;
        int h = w * 32 + t * 8 + (lane >> 2);
        g_W0f[i] = f2tf32(Wpre[k * H_ + h] * s0[h]);
    }

    // W1 (both halves), W2, W3 (8 k-steps each)
    for (int i = tid; i < 4096; i += blockDim.x) {
        int r = i & 1, lane = (i >> 1) & 31, t = (i >> 6) & 3, kt = (i >> 8) & 7, w = (i >> 11) & 1;
        int k = kt * 8 + (lane & 3) + r * 4;
        int h = w * 32 + t * 8 + (lane >> 2);
        g_W1f[i]  = f2tf32(W1[k * H_ + h] * s1[h]);
        g_W1hf[i] = f2tf32(W1[(H_ + k) * H_ + h] * s1[h]);
        g_W2f[i]  = f2tf32(W2[k * H_ + h] * s2[h]);
        g_W3f[i]  = f2tf32(W3[k * H_ + h]);
    }

    // W4 [64][128]: 8 k-steps x 16 n-tiles
    for (int i = tid; i < 8192; i += blockDim.x) {
        int r = i & 1, lane = (i >> 1) & 31, tt = (i >> 6) & 15, kt = (i >> 10) & 7;
        int k = kt * 8 + (lane & 3) + r * 4;
        int o = tt * 8 + (lane >> 2);
        g_W4f[i] = f2tf32(W4[k * OUT_ + o]);
    }

    // Parallel mask dtype sniff (first 1024 bytes).
    {
        const unsigned char* mb = (const unsigned char*)mask;
        unsigned mx = 0, off = 0, al = 0;
        for (int i = tid * 4; i < tid * 4 + 4; i++) {
            unsigned v = mb[i];
            mx |= v;
            if ((i & 3) != 0) off |= v; else al |= v;
        }
        atomicOr(&red[0], mx);
        atomicOr(&red[1], off);
        atomicOr(&red[2], al);
        __syncthreads();
        if (tid == 0)
            g_mask4 = (red[0] > 1u) || (red[1] == 0u && red[2] != 0u);
    }
}

// ============================================================
// Fused encoder: 4 polylines per CTA, 256 threads (8 warps).
// Warps 2p, 2p+1 run polyline slot p's per-point stages (N-halves w=0/1).
// M=4 cross-poly GEMMs (sT / W3 / W4) use all 8 warps as N-tiles.
// ============================================================
__global__ __launch_bounds__(256) void pnet_kernel(
    const float* __restrict__ poly,   // [NPOLY, N, C]
    const void*  __restrict__ mask,   // [NPOLY, N]
    const float* __restrict__ b3,     // [H]
    const float* __restrict__ b4,     // [OUT]
    float*       __restrict__ out,    // [NPOLY, OUT]
    int npoly)
{
    __shared__ __align__(16) uint32_t sA[4 * N_ * SAW];   // X0 / X1 tf32 per poly
    __shared__ __align__(16) uint32_t sP[4 * N_ * SPW];   // padded input tf32
    __shared__ float    sM[4 * N_];
    __shared__ float    sPool1[4 * SVW];
    __shared__ float    sT[4 * SVW];
    __shared__ float    sPool3[4 * SVW];
    __shared__ uint32_t sH4[4 * SVW];
    __shared__ __align__(16) float sOut[4 * 132];
    __shared__ int      sValid[4];

    const int tid  = threadIdx.x;
    const int lane = tid & 31;
    const int wid  = tid >> 5;
    const int p    = wid >> 1;      // poly slot
    const int w    = wid & 1;       // N-half for per-poly stages
    const int pid  = blockIdx.x * 4 + p;
    const int r0   = lane >> 2;
    const int c0   = lane & 3;
    const bool vp  = pid < npoly;

    // ---------------- phase 0: load points + mask ----------------
    {
        const float* pp = poly + (size_t)pid * (N_ * C_);
        uint32_t* sPp = sP + p * (N_ * SPW);
        int q = w * 32 + lane;
        for (int i = q; i < N_ * C_; i += 64) {
            float v = vp ? pp[i] : 0.0f;
            int n = i / C_, c = i - n * C_;
            sPp[n * SPW + c] = f2tf32(v);
        }
        if (q < N_) {
            bool valid = false;
            if (vp) {
                size_t idx = (size_t)pid * N_ + q;
                valid = g_mask4 ? (((const unsigned*)mask)[idx] != 0u)
                                : (((const unsigned char*)mask)[idx] != 0u);
            }
            sM[p * N_ + q] = valid ? 1.0f : 0.0f;
            if (q == 0) sValid[p] = 0;
        }
    }
    __syncthreads();
    {
        int q = w * 32 + lane;
        if (q < N_ && sM[p * N_ + q] != 0.0f) sValid[p] = 1;  // benign: all store 1
    }

    float acc[2][4][4];

    // ---------------- stage 1: X0 = relu(P @ Wpre' + b0') * mask ----------------
    {
        const uint32_t* sPp = sP + p * (N_ * SPW);
        #pragma unroll
        for (int t = 0; t < 4; t++) {
            int hc = w * 32 + t * 8 + c0 * 2;
            float v0 = g_b0v[hc], v1 = g_b0v[hc + 1];
            #pragma unroll
            for (int m = 0; m < 2; m++) {
                acc[m][t][0] = v0; acc[m][t][1] = v1;
                acc[m][t][2] = v0; acc[m][t][3] = v1;
            }
        }
        uint32_t a[2][4];
        #pragma unroll
        for (int m = 0; m < 2; m++) {
            int base = (m * 16 + r0) * SPW + c0;
            a[m][0] = sPp[base];
            a[m][1] = sPp[base + 8 * SPW];
            a[m][2] = sPp[base + 4];
            a[m][3] = sPp[base + 8 * SPW + 4];
        }
        const uint32_t* Wf = g_W0f + w * 256;
        #pragma unroll
        for (int t = 0; t < 4; t++) {
            uint2 b = *(const uint2*)(Wf + (t * 32 + lane) * 2);
            #pragma unroll
            for (int m = 0; m < 2; m++)
                mma_tf32(acc[m][t][0], acc[m][t][1], acc[m][t][2], acc[m][t][3],
                         a[m][0], a[m][1], a[m][2], a[m][3], b.x, b.y);
        }
        // scalar residual: k = 8
        #pragma unroll
        for (int m = 0; m < 2; m++) {
            float x0 = __uint_as_float(sPp[(m * 16 + r0) * SPW + 8]);
            float x1 = __uint_as_float(sPp[(m * 16 + r0 + 8) * SPW + 8]);
            #pragma unroll
            for (int t = 0; t < 4; t++) {
                int hc = w * 32 + t * 8 + c0 * 2;
                float wa = g_Wpre8[hc], wb = g_Wpre8[hc + 1];
                acc[m][t][0] = fmaf(x0, wa, acc[m][t][0]);
                acc[m][t][1] = fmaf(x0, wb, acc[m][t][1]);
                acc[m][t][2] = fmaf(x1, wa, acc[m][t][2]);
                acc[m][t][3] = fmaf(x1, wb, acc[m][t][3]);
            }
        }
        // epilogue: relu*mask, store tf32 X0, pool in regs
        uint32_t* sAp = sA + p * (N_ * SAW);
        float p0[4] = {0, 0, 0, 0}, p1[4] = {0, 0, 0, 0};
        #pragma unroll
        for (int m = 0; m < 2; m++) {
            float rm0 = sM[p * N_ + m * 16 + r0];
            float rm1 = sM[p * N_ + m * 16 + r0 + 8];
            #pragma unroll
            for (int t = 0; t < 4; t++) {
                int hc = w * 32 + t * 8 + c0 * 2;
                int nb = (m * 16 + r0) * SAW;
                float v0 = fmaxf(acc[m][t][0], 0.0f) * rm0;
                float v1 = fmaxf(acc[m][t][1], 0.0f) * rm0;
                float v2 = fmaxf(acc[m][t][2], 0.0f) * rm1;
                float v3 = fmaxf(acc[m][t][3], 0.0f) * rm1;
                sAp[nb + hc]               = f2tf32(v0);
                sAp[nb + hc + 1]           = f2tf32(v1);
                sAp[nb + 8 * SAW + hc]     = f2tf32(v2);
                sAp[nb + 8 * SAW + hc + 1] = f2tf32(v3);
                p0[t] = fmaxf(p0[t], fmaxf(v0, v2));
                p1[t] = fmaxf(p1[t], fmaxf(v1, v3));
            }
        }
        #pragma unroll
        for (int s = 4; s < 32; s <<= 1) {
            #pragma unroll
            for (int t = 0; t < 4; t++) {
                p0[t] = fmaxf(p0[t], __shfl_xor_sync(0xFFFFFFFFu, p0[t], s));
                p1[t] = fmaxf(p1[t], __shfl_xor_sync(0xFFFFFFFFu, p1[t], s));
            }
        }
        if (r0 == 0) {
            #pragma unroll
            for (int t = 0; t < 4; t++) {
                int hc = w * 32 + t * 8 + c0 * 2;
                sPool1[p * SVW + hc]     = p0[t];
                sPool1[p * SVW + hc + 1] = p1[t];
            }
        }
    }
    __syncthreads();

    // ---------------- sT = b1' + pooled1 @ W1_hi  (M=4, all 8 warps) ----------------
    {
        const int tw = wid >> 2, tt4 = wid & 3;
        const int hc = wid * 8 + c0 * 2;
        float d0 = g_b1v[hc], d1 = g_b1v[hc + 1], d2 = 0.0f, d3 = 0.0f;
        #pragma unroll
        for (int kt = 0; kt < 8; kt++) {
            uint32_t a0 = 0, a2 = 0;
            if (r0 < 4) {
                a0 = f2tf32(sPool1[r0 * SVW + kt * 8 + c0]);
                a2 = f2tf32(sPool1[r0 * SVW + kt * 8 + c0 + 4]);
            }
            uint2 b = *(const uint2*)(g_W1hf + (((tw * 8 + kt) * 4 + tt4) * 32 + lane) * 2);
            mma_tf32(d0, d1, d2, d3, a0, 0u, a2, 0u, b.x, b.y);
        }
        if (r0 < 4) {
            sT[r0 * SVW + hc]     = d0;
            sT[r0 * SVW + hc + 1] = d1;
        }
    }
    __syncthreads();

    // ---------------- stage 2: X1 = relu(X0 @ W1_lo + t) * mask ----------------
    {
        uint32_t* sAp = sA + p * (N_ * SAW);
        #pragma unroll
        for (int t = 0; t < 4; t++) {
            int hc = w * 32 + t * 8 + c0 * 2;
            float v0 = sT[p * SVW + hc], v1 = sT[p * SVW + hc + 1];
            #pragma unroll
            for (int m = 0; m < 2; m++) {
                acc[m][t][0] = v0; acc[m][t][1] = v1;
                acc[m][t][2] = v0; acc[m][t][3] = v1;
            }
        }
        const uint32_t* Wf = g_W1f + w * 2048;
        #pragma unroll
        for (int kt = 0; kt < 8; kt++) {
            uint32_t a[2][4];
            #pragma unroll
            for (int m = 0; m < 2; m++) {
                int base = (m * 16 + r0) * SAW + kt * 8 + c0;
                a[m][0] = sAp[base];
                a[m][1] = sAp[base + 8 * SAW];
                a[m][2] = sAp[base + 4];
                a[m][3] = sAp[base + 8 * SAW + 4];
            }
            #pragma unroll
            for (int t = 0; t < 4; t++) {
                uint2 b = *(const uint2*)(Wf + ((kt * 4 + t) * 32 + lane) * 2);
                #pragma unroll
                for (int m = 0; m < 2; m++)
                    mma_tf32(acc[m][t][0], acc[m][t][1], acc[m][t][2], acc[m][t][3],
                             a[m][0], a[m][1], a[m][2], a[m][3], b.x, b.y);
            }
        }
    }
    __syncthreads();   // all reads of X0 complete before in-place X1 store
    {
        uint32_t* sAp = sA + p * (N_ * SAW);
        #pragma unroll
        for (int m = 0; m < 2; m++) {
            float rm0 = sM[p * N_ + m * 16 + r0];
            float rm1 = sM[p * N_ + m * 16 + r0 + 8];
            #pragma unroll
            for (int t = 0; t < 4; t++) {
                int hc = w * 32 + t * 8 + c0 * 2;
                int nb = (m * 16 + r0) * SAW;
                sAp[nb + hc]               = f2tf32(fmaxf(acc[m][t][0], 0.0f) * rm0);
                sAp[nb + hc + 1]           = f2tf32(fmaxf(acc[m][t][1], 0.0f) * rm0);
                sAp[nb + 8 * SAW + hc]     = f2tf32(fmaxf(acc[m][t][2], 0.0f) * rm1);
                sAp[nb + 8 * SAW + hc + 1] = f2tf32(fmaxf(acc[m][t][3], 0.0f) * rm1);
            }
        }
    }
    __syncthreads();

    // ---------------- stage 3: relu(X1 @ W2 + b2') * mask -> pool (regs only) ----------------
    {
        const uint32_t* sAp = sA + p * (N_ * SAW);
        #pragma unroll
        for (int t = 0; t < 4; t++) {
            int hc = w * 32 + t * 8 + c0 * 2;
            float v0 = g_b2v[hc], v1 = g_b2v[hc + 1];
            #pragma unroll
            for (int m = 0; m < 2; m++) {
                acc[m][t][0] = v0; acc[m][t][1] = v1;
                acc[m][t][2] = v0; acc[m][t][3] = v1;
            }
        }
        const uint32_t* Wf = g_W2f + w * 2048;
        #pragma unroll
        for (int kt = 0; kt < 8; kt++) {
            uint32_t a[2][4];
            #pragma unroll
            for (int m = 0; m < 2; m++) {
                int base = (m * 16 + r0) * SAW + kt * 8 + c0;
                a[m][0] = sAp[base];
                a[m][1] = sAp[base + 8 * SAW];
                a[m][2] = sAp[base + 4];
                a[m][3] = sAp[base + 8 * SAW + 4];
            }
            #pragma unroll
            for (int t = 0; t < 4; t++) {
                uint2 b = *(const uint2*)(Wf + ((kt * 4 + t) * 32 + lane) * 2);
                #pragma unroll
                for (int m = 0; m < 2; m++)
                    mma_tf32(acc[m][t][0], acc[m][t][1], acc[m][t][2], acc[m][t][3],
                             a[m][0], a[m][1], a[m][2], a[m][3], b.x, b.y);
            }
        }
        // epilogue: relu*mask -> pool via shfl (no X2 store)
        float p0[4] = {0, 0, 0, 0}, p1[4] = {0, 0, 0, 0};
        #pragma unroll
        for (int m = 0; m < 2; m++) {
            float rm0 = sM[p * N_ + m * 16 + r0];
            float rm1 = sM[p * N_ + m * 16 + r0 + 8];
            #pragma unroll
            for (int t = 0; t < 4; t++) {
                p0[t] = fmaxf(p0[t], fmaxf(fmaxf(acc[m][t][0], 0.0f) * rm0,
                                           fmaxf(acc[m][t][2], 0.0f) * rm1));
                p1[t] = fmaxf(p1[t], fmaxf(fmaxf(acc[m][t][1], 0.0f) * rm0,
                                           fmaxf(acc[m][t][3], 0.0f) * rm1));
            }
        }
        #pragma unroll
        for (int s = 4; s < 32; s <<= 1) {
            #pragma unroll
            for (int t = 0; t < 4; t++) {
                p0[t] = fmaxf(p0[t], __shfl_xor_sync(0xFFFFFFFFu, p0[t], s));
                p1[t] = fmaxf(p1[t], __shfl_xor_sync(0xFFFFFFFFu, p1[t], s));
            }
        }
        if (r0 == 0) {
            #pragma unroll
            for (int t = 0; t < 4; t++) {
                int hc = w * 32 + t * 8 + c0 * 2;
                sPool3[p * SVW + hc]     = p0[t];
                sPool3[p * SVW + hc + 1] = p1[t];
            }
        }
    }
    __syncthreads();

    // ---------------- head part 1: H4 = relu(pooled3 @ W3 + b3)  (M=4) ----------------
    {
        const int tw = wid >> 2, tt4 = wid & 3;
        const int hc = wid * 8 + c0 * 2;
        float d0 = b3[hc], d1 = b3[hc + 1], d2 = 0.0f, d3 = 0.0f;
        #pragma unroll
        for (int kt = 0; kt < 8; kt++) {
            uint32_t a0 = 0, a2 = 0;
            if (r0 < 4) {
                a0 = f2tf32(sPool3[r0 * SVW + kt * 8 + c0]);
                a2 = f2tf32(sPool3[r0 * SVW + kt * 8 + c0 + 4]);
            }
            uint2 b = *(const uint2*)(g_W3f + (((tw * 8 + kt) * 4 + tt4) * 32 + lane) * 2);
            mma_tf32(d0, d1, d2, d3, a0, 0u, a2, 0u, b.x, b.y);
        }
        if (r0 < 4) {
            sH4[r0 * SVW + hc]     = f2tf32(fmaxf(d0, 0.0f));
            sH4[r0 * SVW + hc + 1] = f2tf32(fmaxf(d1, 0.0f));
        }
    }
    __syncthreads();

    // ---------------- head part 2: out = (H4 @ W4 + b4) * anyvalid  (M=4, N=128) ----------------
    {
        const int tt0 = wid * 2;
        float e0[2], e1[2], e2[2], e3[2];
        #pragma unroll
        for (int j = 0; j < 2; j++) {
            int o = (tt0 + j) * 8 + c0 * 2;
            e0[j] = b4[o]; e1[j] = b4[o + 1]; e2[j] = 0.0f; e3[j] = 0.0f;
        }
        #pragma unroll
        for (int kt = 0; kt < 8; kt++) {
            uint32_t a0 = 0, a2 = 0;
            if (r0 < 4) {
                a0 = sH4[r0 * SVW + kt * 8 + c0];
                a2 = sH4[r0 * SVW + kt * 8 + c0 + 4];
            }
            #pragma unroll
            for (int j = 0; j < 2; j++) {
                uint2 b = *(const uint2*)(g_W4f + ((kt * 16 + tt0 + j) * 32 + lane) * 2);
                mma_tf32(e0[j], e1[j], e2[j], e3[j], a0, 0u, a2, 0u, b.x, b.y);
            }
        }
        if (r0 < 4) {
            float vf = sValid[r0] ? 1.0f : 0.0f;
            #pragma unroll
            for (int j = 0; j < 2; j++) {
                int o = (tt0 + j) * 8 + c0 * 2;
                sOut[r0 * 132 + o]     = e0[j] * vf;
                sOut[r0 * 132 + o + 1] = e1[j] * vf;
            }
        }
    }
    __syncthreads();

    // ---------------- coalesced store ----------------
    if (tid < 128) {
        int pp = tid >> 5, j = tid & 31;
        int opid = blockIdx.x * 4 + pp;
        if (opid < npoly) {
            float4 v = *(const float4*)(sOut + pp * 132 + j * 4);
            *(float4*)(out + (size_t)opid * OUT_ + j * 4) = v;
        }
    }
}

// ============================================================
// Launch
// ============================================================
extern "C" void kernel_launch(void* const* d_in, const int* in_sizes, int n_in,
                              void* d_out, int out_size)
{
    const float* poly = (const float*)d_in[0];
    const float* Wpre = (const float*)d_in[1];
    const float* g0   = (const float*)d_in[2];
    const float* b0   = (const float*)d_in[3];
    const float* m0   = (const float*)d_in[4];
    const float* v0   = (const float*)d_in[5];
    const float* W1   = (const float*)d_in[6];
    const float* g1   = (const float*)d_in[7];
    const float* bb1  = (const float*)d_in[8];
    const float* m1   = (const float*)d_in[9];
    const float* v1   = (const float*)d_in[10];
    const float* W2   = (const float*)d_in[11];
    const float* g2   = (const float*)d_in[12];
    const float* bb2  = (const float*)d_in[13];
    const float* m2   = (const float*)d_in[14];
    const float* v2   = (const float*)d_in[15];
    const float* W3   = (const float*)d_in[16];
    const float* b3   = (const float*)d_in[17];
    const float* W4   = (const float*)d_in[18];
    const float* b4   = (const float*)d_in[19];
    const void*  mask = d_in[20];

    const int npoly = in_sizes[0] / (N_ * C_);

    fold_kernel<<<1, 256>>>(Wpre, g0, b0, m0, v0,
                            W1, g1, bb1, m1, v1,
                            W2, g2, bb2, m2, v2, W3, W4, mask);
    pnet_kernel<<<(npoly + 3) / 4, 256>>>(poly, mask, b3, b4, (float*)d_out, npoly);
}

// round 6
// speedup vs baseline: 4.5494x; 1.4272x over previous
#include <cuda_runtime.h>
#include <cuda_fp16.h>
#include <cstdint>

#define BN_EPS 1e-5f

constexpr int N_    = 32;   // points per polyline
constexpr int C_    = 9;    // input channels
constexpr int H_    = 64;   // hidden
constexpr int OUT_  = 128;
constexpr int SAWH  = 36;   // X tile row stride in half2-words (32 data + 4 pad) -> 4r0+c0 conflict-free
constexpr int SPWH  = 12;   // P tile row stride in half2-words (8 data + 4 pad) -> 12r0+c0 conflict-free
constexpr int SVW   = 68;   // stride for [4][64] f32 vector mats

// -------- device scratch (no allocations allowed) --------
__device__ float    g_b0v[H_], g_b1v[H_], g_b2v[H_];
__device__ uint32_t g_W0h[512];         // folded Wpre (k padded to 16), fp16 B-frag
__device__ uint32_t g_W1h[2048];        // folded W1 low half, fp16 B-frag
__device__ uint32_t g_W2h[2048];        // folded W2, fp16 B-frag
__device__ uint32_t g_W1hf[4096];       // folded W1 high half, tf32 B-frag
__device__ uint32_t g_W3f[4096];        // raw W3, tf32 B-frag
__device__ uint32_t g_W4f[8192];        // raw W4 [64][128], tf32 B-frag
__device__ int      g_mask4;            // 1 if mask elements are 4 bytes wide

__device__ __forceinline__ uint32_t f2tf32(float x) {
    uint32_t r;
    asm("cvt.rna.tf32.f32 %0, %1;" : "=r"(r) : "f"(x));
    return r;
}
__device__ __forceinline__ uint32_t packh2(float a, float b) {
    __half2 h = __floats2half2_rn(a, b);
    return *(uint32_t*)&h;
}

__device__ __forceinline__ void mma_tf32(float& c0, float& c1, float& c2, float& c3,
                                         uint32_t a0, uint32_t a1, uint32_t a2, uint32_t a3,
                                         uint32_t b0, uint32_t b1) {
    asm volatile(
        "mma.sync.aligned.m16n8k8.row.col.f32.tf32.tf32.f32 "
        "{%0,%1,%2,%3},{%4,%5,%6,%7},{%8,%9},{%0,%1,%2,%3};\n"
        : "+f"(c0), "+f"(c1), "+f"(c2), "+f"(c3)
        : "r"(a0), "r"(a1), "r"(a2), "r"(a3), "r"(b0), "r"(b1));
}
__device__ __forceinline__ void mma_f16(float& c0, float& c1, float& c2, float& c3,
                                        uint32_t a0, uint32_t a1, uint32_t a2, uint32_t a3,
                                        uint32_t b0, uint32_t b1) {
    asm volatile(
        "mma.sync.aligned.m16n8k16.row.col.f32.f16.f16.f32 "
        "{%0,%1,%2,%3},{%4,%5,%6,%7},{%8,%9},{%0,%1,%2,%3};\n"
        : "+f"(c0), "+f"(c1), "+f"(c2), "+f"(c3)
        : "r"(a0), "r"(a1), "r"(a2), "r"(a3), "r"(b0), "r"(b1));
}

// ============================================================
// Fold BN into weights, build fragment tables, sniff mask dtype.
// ============================================================
__global__ void fold_kernel(const float* __restrict__ Wpre,
                            const float* __restrict__ g0,  const float* __restrict__ b0,
                            const float* __restrict__ m0,  const float* __restrict__ v0,
                            const float* __restrict__ W1,
                            const float* __restrict__ g1,  const float* __restrict__ bb1,
                            const float* __restrict__ m1,  const float* __restrict__ v1,
                            const float* __restrict__ W2,
                            const float* __restrict__ g2,  const float* __restrict__ bb2,
                            const float* __restrict__ m2,  const float* __restrict__ v2,
                            const float* __restrict__ W3,
                            const float* __restrict__ W4,
                            const void*  __restrict__ mask)
{
    __shared__ float s0[H_], s1[H_], s2[H_];
    __shared__ unsigned red[3];
    const int tid = threadIdx.x;

    if (tid < 3) red[tid] = 0u;
    if (tid < H_) {
        float sc0 = g0[tid] * rsqrtf(v0[tid] + BN_EPS);
        float sc1 = g1[tid] * rsqrtf(v1[tid] + BN_EPS);
        float sc2 = g2[tid] * rsqrtf(v2[tid] + BN_EPS);
        s0[tid] = sc0; s1[tid] = sc1; s2[tid] = sc2;
        g_b0v[tid] = b0[tid]  - m0[tid] * sc0;
        g_b1v[tid] = bb1[tid] - m1[tid] * sc1;
        g_b2v[tid] = bb2[tid] - m2[tid] * sc2;
    }
    __syncthreads();

    // fp16 B-frag (m16n8k16): reg r holds half2 {W[k0][h], W[k0+1][h]},
    // k0 = kt*16 + (lane&3)*2 + r*8, h = w*32 + t*8 + (lane>>2)

    // Wpre (single k-step, C=9 zero-padded to 16)
    for (int i = tid; i < 512; i += blockDim.x) {
        int r = i & 1, lane = (i >> 1) & 31, t = (i >> 6) & 3, w = (i >> 8) & 1;
        int k0 = (lane & 3) * 2 + r * 8;
        int h  = w * 32 + t * 8 + (lane >> 2);
        float va = (k0     < C_) ? Wpre[k0 * H_ + h]       * s0[h] : 0.0f;
        float vb = (k0 + 1 < C_) ? Wpre[(k0 + 1) * H_ + h] * s0[h] : 0.0f;
        g_W0h[i] = packh2(va, vb);
    }

    // W1 low half + W2, fp16 frags (4 k-steps of 16)
    for (int i = tid; i < 2048; i += blockDim.x) {
        int r = i & 1, lane = (i >> 1) & 31, t = (i >> 6) & 3, kt = (i >> 8) & 3, w = (i >> 10) & 1;
        int k0 = kt * 16 + (lane & 3) * 2 + r * 8;
        int h  = w * 32 + t * 8 + (lane >> 2);
        g_W1h[i] = packh2(W1[k0 * H_ + h] * s1[h], W1[(k0 + 1) * H_ + h] * s1[h]);
        g_W2h[i] = packh2(W2[k0 * H_ + h] * s2[h], W2[(k0 + 1) * H_ + h] * s2[h]);
    }

    // tf32 B-frag (m16n8k8): k = kt*8 + (lane&3) + r*4
    for (int i = tid; i < 4096; i += blockDim.x) {
        int r = i & 1, lane = (i >> 1) & 31, t = (i >> 6) & 3, kt = (i >> 8) & 7, w = (i >> 11) & 1;
        int k = kt * 8 + (lane & 3) + r * 4;
        int h = w * 32 + t * 8 + (lane >> 2);
        g_W1hf[i] = f2tf32(W1[(H_ + k) * H_ + h] * s1[h]);
        g_W3f[i]  = f2tf32(W3[k * H_ + h]);
    }

    // W4 [64][128]: 8 k-steps x 16 n-tiles (tf32)
    for (int i = tid; i < 8192; i += blockDim.x) {
        int r = i & 1, lane = (i >> 1) & 31, tt = (i >> 6) & 15, kt = (i >> 10) & 7;
        int k = kt * 8 + (lane & 3) + r * 4;
        int o = tt * 8 + (lane >> 2);
        g_W4f[i] = f2tf32(W4[k * OUT_ + o]);
    }

    // Parallel mask dtype sniff (first 1024 bytes).
    {
        const unsigned char* mb = (const unsigned char*)mask;
        unsigned mx = 0, off = 0, al = 0;
        for (int i = tid * 4; i < tid * 4 + 4; i++) {
            unsigned v = mb[i];
            mx |= v;
            if ((i & 3) != 0) off |= v; else al |= v;
        }
        atomicOr(&red[0], mx);
        atomicOr(&red[1], off);
        atomicOr(&red[2], al);
        __syncthreads();
        if (tid == 0)
            g_mask4 = (red[0] > 1u) || (red[1] == 0u && red[2] != 0u);
    }
}

// ============================================================
// Fused encoder: 4 polylines per CTA, 256 threads (8 warps).
// Stages 1/2/3 in fp16 mma (f32 acc); sT + head in tf32 mma.
// ============================================================
__global__ __launch_bounds__(256, 4) void pnet_kernel(
    const float* __restrict__ poly,   // [NPOLY, N, C]
    const void*  __restrict__ mask,   // [NPOLY, N]
    const float* __restrict__ b3,     // [H]
    const float* __restrict__ b4,     // [OUT]
    float*       __restrict__ out,    // [NPOLY, OUT]
    int npoly)
{
    __shared__ __align__(16) uint32_t sA[4 * N_ * SAWH];  // X0 / X1 half2 per poly
    __shared__ __align__(16) uint32_t sP[4 * N_ * SPWH];  // padded input half2
    __shared__ float    sM[4 * N_];
    __shared__ float    sPool1[4 * SVW];
    __shared__ float    sT[4 * SVW];
    __shared__ float    sPool3[4 * SVW];
    __shared__ uint32_t sH4[4 * SVW];
    __shared__ __align__(16) float sOut[4 * 132];
    __shared__ int      sValid[4];

    const int tid  = threadIdx.x;
    const int lane = tid & 31;
    const int wid  = tid >> 5;
    const int p    = wid >> 1;      // poly slot
    const int w    = wid & 1;       // N-half / h-half
    const int pid  = blockIdx.x * 4 + p;
    const int r0   = lane >> 2;
    const int c0   = lane & 3;
    const bool vp  = pid < npoly;

    uint32_t* const sAp = sA + p * (N_ * SAWH);
    uint32_t* const sPp = sP + p * (N_ * SPWH);

    // ---------------- phase 0: load points (fp16, zero-padded k) + mask ----------------
    {
        const float* pp = poly + (size_t)pid * (N_ * C_);
        __half* sPh = (__half*)sPp;
        int q = w * 32 + lane;
        for (int i = q; i < N_ * 16; i += 64) {
            int n = i >> 4, c = i & 15;
            float v = (vp && c < C_) ? pp[n * C_ + c] : 0.0f;
            sPh[n * (2 * SPWH) + c] = __float2half_rn(v);
        }
        if (q < N_) {
            bool valid = false;
            if (vp) {
                size_t idx = (size_t)pid * N_ + q;
                valid = g_mask4 ? (((const unsigned*)mask)[idx] != 0u)
                                : (((const unsigned char*)mask)[idx] != 0u);
            }
            sM[p * N_ + q] = valid ? 1.0f : 0.0f;
            if (q == 0) sValid[p] = 0;
        }
    }
    __syncthreads();
    {
        int q = w * 32 + lane;
        if (q < N_ && sM[p * N_ + q] != 0.0f) sValid[p] = 1;  // benign: all store 1
    }

    float acc[2][4][4];

    // ---------------- stage 1: X0 = relu(P @ Wpre' + b0') * mask (1 k-step) ----------------
    {
        #pragma unroll
        for (int t = 0; t < 4; t++) {
            int hc = w * 32 + t * 8 + c0 * 2;
            float v0 = g_b0v[hc], v1 = g_b0v[hc + 1];
            #pragma unroll
            for (int m = 0; m < 2; m++) {
                acc[m][t][0] = v0; acc[m][t][1] = v1;
                acc[m][t][2] = v0; acc[m][t][3] = v1;
            }
        }
        uint32_t a[2][4];
        #pragma unroll
        for (int m = 0; m < 2; m++) {
            int base = (m * 16 + r0) * SPWH + c0;
            a[m][0] = sPp[base];
            a[m][1] = sPp[base + 8 * SPWH];
            a[m][2] = sPp[base + 4];
            a[m][3] = sPp[base + 8 * SPWH + 4];
        }
        const uint32_t* Wf = g_W0h + w * 256;
        #pragma unroll
        for (int t = 0; t < 4; t++) {
            uint2 b = *(const uint2*)(Wf + (t * 32 + lane) * 2);
            #pragma unroll
            for (int m = 0; m < 2; m++)
                mma_f16(acc[m][t][0], acc[m][t][1], acc[m][t][2], acc[m][t][3],
                        a[m][0], a[m][1], a[m][2], a[m][3], b.x, b.y);
        }
        // epilogue: relu*mask, store half2 X0, pool in regs
        float p0[4] = {0, 0, 0, 0}, p1[4] = {0, 0, 0, 0};
        #pragma unroll
        for (int m = 0; m < 2; m++) {
            float rm0 = sM[p * N_ + m * 16 + r0];
            float rm1 = sM[p * N_ + m * 16 + r0 + 8];
            #pragma unroll
            for (int t = 0; t < 4; t++) {
                int wc = w * 16 + t * 4 + c0;             // half2 word for (hc, hc+1)
                int nb = (m * 16 + r0) * SAWH;
                float v0 = fmaxf(acc[m][t][0], 0.0f) * rm0;
                float v1 = fmaxf(acc[m][t][1], 0.0f) * rm0;
                float v2 = fmaxf(acc[m][t][2], 0.0f) * rm1;
                float v3 = fmaxf(acc[m][t][3], 0.0f) * rm1;
                sAp[nb + wc]            = packh2(v0, v1);
                sAp[nb + 8 * SAWH + wc] = packh2(v2, v3);
                p0[t] = fmaxf(p0[t], fmaxf(v0, v2));
                p1[t] = fmaxf(p1[t], fmaxf(v1, v3));
            }
        }
        #pragma unroll
        for (int s = 4; s < 32; s <<= 1) {
            #pragma unroll
            for (int t = 0; t < 4; t++) {
                p0[t] = fmaxf(p0[t], __shfl_xor_sync(0xFFFFFFFFu, p0[t], s));
                p1[t] = fmaxf(p1[t], __shfl_xor_sync(0xFFFFFFFFu, p1[t], s));
            }
        }
        if (r0 == 0) {
            #pragma unroll
            for (int t = 0; t < 4; t++) {
                int hc = w * 32 + t * 8 + c0 * 2;
                sPool1[p * SVW + hc]     = p0[t];
                sPool1[p * SVW + hc + 1] = p1[t];
            }
        }
    }
    __syncthreads();

    // ---------------- sT = b1' + pooled1 @ W1_hi  (tf32, M=4, all 8 warps) ----------------
    {
        const int tw = wid >> 2, tt4 = wid & 3;
        const int hc = wid * 8 + c0 * 2;
        float d0 = g_b1v[hc], d1 = g_b1v[hc + 1], d2 = 0.0f, d3 = 0.0f;
        #pragma unroll
        for (int kt = 0; kt < 8; kt++) {
            uint32_t a0 = 0, a2 = 0;
            if (r0 < 4) {
                a0 = f2tf32(sPool1[r0 * SVW + kt * 8 + c0]);
                a2 = f2tf32(sPool1[r0 * SVW + kt * 8 + c0 + 4]);
            }
            uint2 b = *(const uint2*)(g_W1hf + (((tw * 8 + kt) * 4 + tt4) * 32 + lane) * 2);
            mma_tf32(d0, d1, d2, d3, a0, 0u, a2, 0u, b.x, b.y);
        }
        if (r0 < 4) {
            sT[r0 * SVW + hc]     = d0;
            sT[r0 * SVW + hc + 1] = d1;
        }
    }
    __syncthreads();

    // ---------------- stage 2: X1 = relu(X0 @ W1_lo + t) * mask ----------------
    {
        #pragma unroll
        for (int t = 0; t < 4; t++) {
            int hc = w * 32 + t * 8 + c0 * 2;
            float v0 = sT[p * SVW + hc], v1 = sT[p * SVW + hc + 1];
            #pragma unroll
            for (int m = 0; m < 2; m++) {
                acc[m][t][0] = v0; acc[m][t][1] = v1;
                acc[m][t][2] = v0; acc[m][t][3] = v1;
            }
        }
        const uint32_t* Wf = g_W1h + w * 1024;
        #pragma unroll
        for (int kt = 0; kt < 4; kt++) {
            uint32_t a[2][4];
            #pragma unroll
            for (int m = 0; m < 2; m++) {
                int base = (m * 16 + r0) * SAWH + kt * 8 + c0;
                a[m][0] = sAp[base];
                a[m][1] = sAp[base + 8 * SAWH];
                a[m][2] = sAp[base + 4];
                a[m][3] = sAp[base + 8 * SAWH + 4];
            }
            #pragma unroll
            for (int t = 0; t < 4; t++) {
                uint2 b = *(const uint2*)(Wf + ((kt * 4 + t) * 32 + lane) * 2);
                #pragma unroll
                for (int m = 0; m < 2; m++)
                    mma_f16(acc[m][t][0], acc[m][t][1], acc[m][t][2], acc[m][t][3],
                            a[m][0], a[m][1], a[m][2], a[m][3], b.x, b.y);
            }
        }
    }
    __syncthreads();   // all reads of X0 complete before in-place X1 store
    {
        #pragma unroll
        for (int m = 0; m < 2; m++) {
            float rm0 = sM[p * N_ + m * 16 + r0];
            float rm1 = sM[p * N_ + m * 16 + r0 + 8];
            #pragma unroll
            for (int t = 0; t < 4; t++) {
                int wc = w * 16 + t * 4 + c0;
                int nb = (m * 16 + r0) * SAWH;
                sAp[nb + wc]            = packh2(fmaxf(acc[m][t][0], 0.0f) * rm0,
                                                fmaxf(acc[m][t][1], 0.0f) * rm0);
                sAp[nb + 8 * SAWH + wc] = packh2(fmaxf(acc[m][t][2], 0.0f) * rm1,
                                                fmaxf(acc[m][t][3], 0.0f) * rm1);
            }
        }
    }
    __syncthreads();

    // ---------------- stage 3: relu(X1 @ W2 + b2') * mask -> pool (regs only) ----------------
    {
        #pragma unroll
        for (int t = 0; t < 4; t++) {
            int hc = w * 32 + t * 8 + c0 * 2;
            float v0 = g_b2v[hc], v1 = g_b2v[hc + 1];
            #pragma unroll
            for (int m = 0; m < 2; m++) {
                acc[m][t][0] = v0; acc[m][t][1] = v1;
                acc[m][t][2] = v0; acc[m][t][3] = v1;
            }
        }
        const uint32_t* Wf = g_W2h + w * 1024;
        #pragma unroll
        for (int kt = 0; kt < 4; kt++) {
            uint32_t a[2][4];
            #pragma unroll
            for (int m = 0; m < 2; m++) {
                int base = (m * 16 + r0) * SAWH + kt * 8 + c0;
                a[m][0] = sAp[base];
                a[m][1] = sAp[base + 8 * SAWH];
                a[m][2] = sAp[base + 4];
                a[m][3] = sAp[base + 8 * SAWH + 4];
            }
            #pragma unroll
            for (int t = 0; t < 4; t++) {
                uint2 b = *(const uint2*)(Wf + ((kt * 4 + t) * 32 + lane) * 2);
                #pragma unroll
                for (int m = 0; m < 2; m++)
                    mma_f16(acc[m][t][0], acc[m][t][1], acc[m][t][2], acc[m][t][3],
                            a[m][0], a[m][1], a[m][2], a[m][3], b.x, b.y);
            }
        }
        // epilogue: relu*mask -> pool via shfl (no X2 store)
        float p0[4] = {0, 0, 0, 0}, p1[4] = {0, 0, 0, 0};
        #pragma unroll
        for (int m = 0; m < 2; m++) {
            float rm0 = sM[p * N_ + m * 16 + r0];
            float rm1 = sM[p * N_ + m * 16 + r0 + 8];
            #pragma unroll
            for (int t = 0; t < 4; t++) {
                p0[t] = fmaxf(p0[t], fmaxf(fmaxf(acc[m][t][0], 0.0f) * rm0,
                                           fmaxf(acc[m][t][2], 0.0f) * rm1));
                p1[t] = fmaxf(p1[t], fmaxf(fmaxf(acc[m][t][1], 0.0f) * rm0,
                                           fmaxf(acc[m][t][3], 0.0f) * rm1));
            }
        }
        #pragma unroll
        for (int s = 4; s < 32; s <<= 1) {
            #pragma unroll
            for (int t = 0; t < 4; t++) {
                p0[t] = fmaxf(p0[t], __shfl_xor_sync(0xFFFFFFFFu, p0[t], s));
                p1[t] = fmaxf(p1[t], __shfl_xor_sync(0xFFFFFFFFu, p1[t], s));
            }
        }
        if (r0 == 0) {
            #pragma unroll
            for (int t = 0; t < 4; t++) {
                int hc = w * 32 + t * 8 + c0 * 2;
                sPool3[p * SVW + hc]     = p0[t];
                sPool3[p * SVW + hc + 1] = p1[t];
            }
        }
    }
    __syncthreads();

    // ---------------- head part 1: H4 = relu(pooled3 @ W3 + b3)  (tf32, M=4) ----------------
    {
        const int tw = wid >> 2, tt4 = wid & 3;
        const int hc = wid * 8 + c0 * 2;
        float d0 = b3[hc], d1 = b3[hc + 1], d2 = 0.0f, d3 = 0.0f;
        #pragma unroll
        for (int kt = 0; kt < 8; kt++) {
            uint32_t a0 = 0, a2 = 0;
            if (r0 < 4) {
                a0 = f2tf32(sPool3[r0 * SVW + kt * 8 + c0]);
                a2 = f2tf32(sPool3[r0 * SVW + kt * 8 + c0 + 4]);
            }
            uint2 b = *(const uint2*)(g_W3f + (((tw * 8 + kt) * 4 + tt4) * 32 + lane) * 2);
            mma_tf32(d0, d1, d2, d3, a0, 0u, a2, 0u, b.x, b.y);
        }
        if (r0 < 4) {
            sH4[r0 * SVW + hc]     = f2tf32(fmaxf(d0, 0.0f));
            sH4[r0 * SVW + hc + 1] = f2tf32(fmaxf(d1, 0.0f));
        }
    }
    __syncthreads();

    // ---------------- head part 2: out = (H4 @ W4 + b4) * anyvalid  (tf32, M=4, N=128) ----------------
    {
        const int tt0 = wid * 2;
        float e0[2], e1[2], e2[2], e3[2];
        #pragma unroll
        for (int j = 0; j < 2; j++) {
            int o = (tt0 + j) * 8 + c0 * 2;
            e0[j] = b4[o]; e1[j] = b4[o + 1]; e2[j] = 0.0f; e3[j] = 0.0f;
        }
        #pragma unroll
        for (int kt = 0; kt < 8; kt++) {
            uint32_t a0 = 0, a2 = 0;
            if (r0 < 4) {
                a0 = sH4[r0 * SVW + kt * 8 + c0];
                a2 = sH4[r0 * SVW + kt * 8 + c0 + 4];
            }
            #pragma unroll
            for (int j = 0; j < 2; j++) {
                uint2 b = *(const uint2*)(g_W4f + ((kt * 16 + tt0 + j) * 32 + lane) * 2);
                mma_tf32(e0[j], e1[j], e2[j], e3[j], a0, 0u, a2, 0u, b.x, b.y);
            }
        }
        if (r0 < 4) {
            float vf = sValid[r0] ? 1.0f : 0.0f;
            #pragma unroll
            for (int j = 0; j < 2; j++) {
                int o = (tt0 + j) * 8 + c0 * 2;
                sOut[r0 * 132 + o]     = e0[j] * vf;
                sOut[r0 * 132 + o + 1] = e1[j] * vf;
            }
        }
    }
    __syncthreads();

    // ---------------- coalesced store ----------------
    if (tid < 128) {
        int pp = tid >> 5, j = tid & 31;
        int opid = blockIdx.x * 4 + pp;
        if (opid < npoly) {
            float4 v = *(const float4*)(sOut + pp * 132 + j * 4);
            *(float4*)(out + (size_t)opid * OUT_ + j * 4) = v;
        }
    }
}

// ============================================================
// Launch
// ============================================================
extern "C" void kernel_launch(void* const* d_in, const int* in_sizes, int n_in,
                              void* d_out, int out_size)
{
    const float* poly = (const float*)d_in[0];
    const float* Wpre = (const float*)d_in[1];
    const float* g0   = (const float*)d_in[2];
    const float* b0   = (const float*)d_in[3];
    const float* m0   = (const float*)d_in[4];
    const float* v0   = (const float*)d_in[5];
    const float* W1   = (const float*)d_in[6];
    const float* g1   = (const float*)d_in[7];
    const float* bb1  = (const float*)d_in[8];
    const float* m1   = (const float*)d_in[9];
    const float* v1   = (const float*)d_in[10];
    const float* W2   = (const float*)d_in[11];
    const float* g2   = (const float*)d_in[12];
    const float* bb2  = (const float*)d_in[13];
    const float* m2   = (const float*)d_in[14];
    const float* v2   = (const float*)d_in[15];
    const float* W3   = (const float*)d_in[16];
    const float* b3   = (const float*)d_in[17];
    const float* W4   = (const float*)d_in[18];
    const float* b4   = (const float*)d_in[19];
    const void*  mask = d_in[20];

    const int npoly = in_sizes[0] / (N_ * C_);

    fold_kernel<<<1, 256>>>(Wpre, g0, b0, m0, v0,
                            W1, g1, bb1, m1, v1,
                            W2, g2, bb2, m2, v2, W3, W4, mask);
    pnet_kernel<<<(npoly + 3) / 4, 256>>>(poly, mask, b3, b4, (float*)d_out, npoly);
}

// round 7
// speedup vs baseline: 5.7968x; 1.2742x over previous
#include <cuda_runtime.h>
#include <cuda_fp16.h>
#include <cstdint>

#define BN_EPS 1e-5f

constexpr int N_    = 32;   // points per polyline
constexpr int C_    = 9;    // input channels
constexpr int H_    = 64;   // hidden
constexpr int OUT_  = 128;
constexpr int SAWH  = 36;   // X tile row stride in half2-words -> conflict-free frags
constexpr int SPWH  = 12;   // P tile row stride in half2-words -> conflict-free
constexpr int SVH   = 36;   // row stride (half2 words) for [4][32] pooled / H4 mats
constexpr int SVW   = 68;   // row stride (f32) for sT

// -------- device scratch (no allocations allowed) --------
__device__ float    g_b0v[H_], g_b1v[H_], g_b2v[H_];
__device__ uint32_t g_W0h[512];         // folded Wpre (k padded to 16), fp16 B-frag
__device__ uint32_t g_W1h[2048];        // folded W1 low half  (k 0..63), fp16 B-frag
__device__ uint32_t g_W1hh[2048];       // folded W1 high half (k 64..127), fp16 B-frag
__device__ uint32_t g_W2h[2048];        // folded W2, fp16 B-frag
__device__ uint32_t g_W3h[2048];        // raw W3, fp16 B-frag
__device__ uint32_t g_W4h[4096];        // raw W4 [64][128], fp16 B-frag
__device__ int      g_mask4;            // 1 if mask elements are 4 bytes wide

__device__ __forceinline__ uint32_t packh2(float a, float b) {
    __half2 h = __floats2half2_rn(a, b);
    return *(uint32_t*)&h;
}
__device__ __forceinline__ uint32_t h2bits(__half2 v) { return *(uint32_t*)&v; }
__device__ __forceinline__ __half2  bits2h(uint32_t u) { return *(__half2*)&u; }

__device__ __forceinline__ void mma_f16(float& c0, float& c1, float& c2, float& c3,
                                        uint32_t a0, uint32_t a1, uint32_t a2, uint32_t a3,
                                        uint32_t b0, uint32_t b1) {
    asm volatile(
        "mma.sync.aligned.m16n8k16.row.col.f32.f16.f16.f32 "
        "{%0,%1,%2,%3},{%4,%5,%6,%7},{%8,%9},{%0,%1,%2,%3};\n"
        : "+f"(c0), "+f"(c1), "+f"(c2), "+f"(c3)
        : "r"(a0), "r"(a1), "r"(a2), "r"(a3), "r"(b0), "r"(b1));
}

#define BARP(id) asm volatile("bar.sync %0, %1;" :: "r"(id), "r"(64) : "memory")

// ============================================================
// Fold BN into weights, build fp16 B-fragment tables, sniff mask dtype.
// ============================================================
__global__ void fold_kernel(const float* __restrict__ Wpre,
                            const float* __restrict__ g0,  const float* __restrict__ b0,
                            const float* __restrict__ m0,  const float* __restrict__ v0,
                            const float* __restrict__ W1,
                            const float* __restrict__ g1,  const float* __restrict__ bb1,
                            const float* __restrict__ m1,  const float* __restrict__ v1,
                            const float* __restrict__ W2,
                            const float* __restrict__ g2,  const float* __restrict__ bb2,
                            const float* __restrict__ m2,  const float* __restrict__ v2,
                            const float* __restrict__ W3,
                            const float* __restrict__ W4,
                            const void*  __restrict__ mask)
{
    __shared__ float s0[H_], s1[H_], s2[H_];
    __shared__ unsigned red[3];
    const int tid = threadIdx.x;

    if (tid < 3) red[tid] = 0u;
    if (tid < H_) {
        float sc0 = g0[tid] * rsqrtf(v0[tid] + BN_EPS);
        float sc1 = g1[tid] * rsqrtf(v1[tid] + BN_EPS);
        float sc2 = g2[tid] * rsqrtf(v2[tid] + BN_EPS);
        s0[tid] = sc0; s1[tid] = sc1; s2[tid] = sc2;
        g_b0v[tid] = b0[tid]  - m0[tid] * sc0;
        g_b1v[tid] = bb1[tid] - m1[tid] * sc1;
        g_b2v[tid] = bb2[tid] - m2[tid] * sc2;
    }
    __syncthreads();

    // fp16 B-frag (m16n8k16): reg r holds half2 {W[k0][h], W[k0+1][h]},
    // k0 = kt*16 + (lane&3)*2 + r*8, h = n-tile*8 + (lane>>2)

    // Wpre (single k-step, C=9 zero-padded to 16)
    for (int i = tid; i < 512; i += blockDim.x) {
        int r = i & 1, lane = (i >> 1) & 31, t = (i >> 6) & 3, w = (i >> 8) & 1;
        int k0 = (lane & 3) * 2 + r * 8;
        int h  = w * 32 + t * 8 + (lane >> 2);
        float va = (k0     < C_) ? Wpre[k0 * H_ + h]       * s0[h] : 0.0f;
        float vb = (k0 + 1 < C_) ? Wpre[(k0 + 1) * H_ + h] * s0[h] : 0.0f;
        g_W0h[i] = packh2(va, vb);
    }

    // W1 (both halves), W2, W3: [64][64] fp16 frags (4 k-steps of 16)
    for (int i = tid; i < 2048; i += blockDim.x) {
        int r = i & 1, lane = (i >> 1) & 31, t = (i >> 6) & 3, kt = (i >> 8) & 3, w = (i >> 10) & 1;
        int k0 = kt * 16 + (lane & 3) * 2 + r * 8;
        int h  = w * 32 + t * 8 + (lane >> 2);
        g_W1h[i]  = packh2(W1[k0 * H_ + h] * s1[h],        W1[(k0 + 1) * H_ + h] * s1[h]);
        g_W1hh[i] = packh2(W1[(H_ + k0) * H_ + h] * s1[h], W1[(H_ + k0 + 1) * H_ + h] * s1[h]);
        g_W2h[i]  = packh2(W2[k0 * H_ + h] * s2[h],        W2[(k0 + 1) * H_ + h] * s2[h]);
        g_W3h[i]  = packh2(W3[k0 * H_ + h],                W3[(k0 + 1) * H_ + h]);
    }

    // W4 [64][128]: 4 k-steps x 16 n-tiles (fp16)
    for (int i = tid; i < 4096; i += blockDim.x) {
        int r = i & 1, lane = (i >> 1) & 31, tt = (i >> 6) & 15, kt = (i >> 10) & 3;
        int k0 = kt * 16 + (lane & 3) * 2 + r * 8;
        int o  = tt * 8 + (lane >> 2);
        g_W4h[i] = packh2(W4[k0 * OUT_ + o], W4[(k0 + 1) * OUT_ + o]);
    }

    // Parallel mask dtype sniff (first 1024 bytes).
    {
        const unsigned char* mb = (const unsigned char*)mask;
        unsigned mx = 0, off = 0, al = 0;
        for (int i = tid * 4; i < tid * 4 + 4; i++) {
            unsigned v = mb[i];
            mx |= v;
            if ((i & 3) != 0) off |= v; else al |= v;
        }
        atomicOr(&red[0], mx);
        atomicOr(&red[1], off);
        atomicOr(&red[2], al);
        __syncthreads();
        if (tid == 0)
            g_mask4 = (red[0] > 1u) || (red[1] == 0u && red[2] != 0u);
    }
}

// ============================================================
// Fused encoder: 4 polylines per CTA, 256 threads (8 warps), all-fp16 mma.
// Per-poly stages sync via named 64-thread barriers; cross-poly GEMMs via
// full __syncthreads.
// ============================================================
__global__ __launch_bounds__(256, 4) void pnet_kernel(
    const float* __restrict__ poly,   // [NPOLY, N, C]
    const void*  __restrict__ mask,   // [NPOLY, N]
    const float* __restrict__ b3,     // [H]
    const float* __restrict__ b4,     // [OUT]
    float*       __restrict__ out,    // [NPOLY, OUT]
    int npoly)
{
    __shared__ __align__(16) uint32_t sA[4 * N_ * SAWH];  // X0 / X1 half2 per poly
    __shared__ __align__(16) uint32_t sP[4 * N_ * SPWH];  // padded input half2
    __shared__ float    sM[4 * N_];
    __shared__ uint32_t sPool1h[4 * SVH];                  // pooled1 as half2 rows
    __shared__ float    sT[4 * SVW];
    __shared__ uint32_t sPool3h[4 * SVH];                  // pooled3 as half2 rows
    __shared__ uint32_t sH4h[4 * SVH];                     // relu(W3 out) as half2 rows
    __shared__ __align__(16) float sOut[4 * 132];
    __shared__ int      sValid[4];

    const int tid  = threadIdx.x;
    const int lane = tid & 31;
    const int wid  = tid >> 5;
    const int p    = wid >> 1;      // poly slot
    const int w    = wid & 1;       // N-half / h-half
    const int pid  = blockIdx.x * 4 + p;
    const int r0   = lane >> 2;
    const int c0   = lane & 3;
    const bool vp  = pid < npoly;
    const __half2 hz = __float2half2_rn(0.0f);

    uint32_t* const sAp = sA + p * (N_ * SAWH);
    uint32_t* const sPp = sP + p * (N_ * SPWH);

    // ---------------- phase 0: load points (fp16, zero-padded k) + mask ----------------
    {
        const float* pp = poly + (size_t)pid * (N_ * C_);
        __half* sPh = (__half*)sPp;
        int q = w * 32 + lane;
        for (int i = q; i < N_ * 16; i += 64) {
            int n = i >> 4, c = i & 15;
            float v = (vp && c < C_) ? pp[n * C_ + c] : 0.0f;
            sPh[n * (2 * SPWH) + c] = __float2half_rn(v);
        }
        if (q < N_) {
            bool valid = false;
            if (vp) {
                size_t idx = (size_t)pid * N_ + q;
                valid = g_mask4 ? (((const unsigned*)mask)[idx] != 0u)
                                : (((const unsigned char*)mask)[idx] != 0u);
            }
            sM[p * N_ + q] = valid ? 1.0f : 0.0f;
            if (q == 0) sValid[p] = 0;
        }
    }
    BARP(1 + p);
    {
        int q = w * 32 + lane;
        if (q < N_ && sM[p * N_ + q] != 0.0f) sValid[p] = 1;  // benign: all store 1
    }

    float acc[2][4][4];

    // ---------------- stage 1: X0 = relu(P @ Wpre' + b0') * mask (1 k-step) ----------------
    {
        #pragma unroll
        for (int t = 0; t < 4; t++) {
            int hc = w * 32 + t * 8 + c0 * 2;
            float v0 = g_b0v[hc], v1 = g_b0v[hc + 1];
            #pragma unroll
            for (int m = 0; m < 2; m++) {
                acc[m][t][0] = v0; acc[m][t][1] = v1;
                acc[m][t][2] = v0; acc[m][t][3] = v1;
            }
        }
        uint32_t a[2][4];
        #pragma unroll
        for (int m = 0; m < 2; m++) {
            int base = (m * 16 + r0) * SPWH + c0;
            a[m][0] = sPp[base];
            a[m][1] = sPp[base + 8 * SPWH];
            a[m][2] = sPp[base + 4];
            a[m][3] = sPp[base + 8 * SPWH + 4];
        }
        const uint32_t* Wf = g_W0h + w * 256;
        #pragma unroll
        for (int t = 0; t < 4; t++) {
            uint2 b = *(const uint2*)(Wf + (t * 32 + lane) * 2);
            #pragma unroll
            for (int m = 0; m < 2; m++)
                mma_f16(acc[m][t][0], acc[m][t][1], acc[m][t][2], acc[m][t][3],
                        a[m][0], a[m][1], a[m][2], a[m][3], b.x, b.y);
        }
        // epilogue: relu*mask + store + pool, all in half2
        uint32_t pm[4] = {0, 0, 0, 0};
        #pragma unroll
        for (int m = 0; m < 2; m++) {
            __half2 mk0 = __float2half2_rn(sM[p * N_ + m * 16 + r0]);
            __half2 mk1 = __float2half2_rn(sM[p * N_ + m * 16 + r0 + 8]);
            #pragma unroll
            for (int t = 0; t < 4; t++) {
                int wc = w * 16 + t * 4 + c0;
                int nb = (m * 16 + r0) * SAWH;
                __half2 a01 = __hmul2(__hmax2(__floats2half2_rn(acc[m][t][0], acc[m][t][1]), hz), mk0);
                __half2 a23 = __hmul2(__hmax2(__floats2half2_rn(acc[m][t][2], acc[m][t][3]), hz), mk1);
                sAp[nb + wc]            = h2bits(a01);
                sAp[nb + 8 * SAWH + wc] = h2bits(a23);
                pm[t] = h2bits(__hmax2(bits2h(pm[t]), __hmax2(a01, a23)));
            }
        }
        #pragma unroll
        for (int s = 4; s < 32; s <<= 1) {
            #pragma unroll
            for (int t = 0; t < 4; t++)
                pm[t] = h2bits(__hmax2(bits2h(pm[t]),
                                       bits2h(__shfl_xor_sync(0xFFFFFFFFu, pm[t], s))));
        }
        if (r0 == 0) {
            #pragma unroll
            for (int t = 0; t < 4; t++)
                sPool1h[p * SVH + w * 16 + t * 4 + c0] = pm[t];
        }
    }
    __syncthreads();

    // ---------------- sT = b1' + pooled1 @ W1_hi  (fp16, M=4, all 8 warps) ----------------
    {
        const int tw = wid >> 2, tt4 = wid & 3;
        const int hc = wid * 8 + c0 * 2;
        float d0 = g_b1v[hc], d1 = g_b1v[hc + 1], d2 = 0.0f, d3 = 0.0f;
        #pragma unroll
        for (int kt = 0; kt < 4; kt++) {
            uint32_t a0 = 0, a2 = 0;
            if (r0 < 4) {
                a0 = sPool1h[r0 * SVH + kt * 8 + c0];
                a2 = sPool1h[r0 * SVH + kt * 8 + 4 + c0];
            }
            uint2 b = *(const uint2*)(g_W1hh + (((tw * 4 + kt) * 4 + tt4) * 32 + lane) * 2);
            mma_f16(d0, d1, d2, d3, a0, 0u, a2, 0u, b.x, b.y);
        }
        if (r0 < 4) {
            sT[r0 * SVW + hc]     = d0;
            sT[r0 * SVW + hc + 1] = d1;
        }
    }
    __syncthreads();

    // ---------------- stage 2: X1 = relu(X0 @ W1_lo + t) * mask ----------------
    {
        #pragma unroll
        for (int t = 0; t < 4; t++) {
            int hc = w * 32 + t * 8 + c0 * 2;
            float v0 = sT[p * SVW + hc], v1 = sT[p * SVW + hc + 1];
            #pragma unroll
            for (int m = 0; m < 2; m++) {
                acc[m][t][0] = v0; acc[m][t][1] = v1;
                acc[m][t][2] = v0; acc[m][t][3] = v1;
            }
        }
        const uint32_t* Wf = g_W1h + w * 1024;
        #pragma unroll
        for (int kt = 0; kt < 4; kt++) {
            uint32_t a[2][4];
            #pragma unroll
            for (int m = 0; m < 2; m++) {
                int base = (m * 16 + r0) * SAWH + kt * 8 + c0;
                a[m][0] = sAp[base];
                a[m][1] = sAp[base + 8 * SAWH];
                a[m][2] = sAp[base + 4];
                a[m][3] = sAp[base + 8 * SAWH + 4];
            }
            #pragma unroll
            for (int t = 0; t < 4; t++) {
                uint2 b = *(const uint2*)(Wf + ((kt * 4 + t) * 32 + lane) * 2);
                #pragma unroll
                for (int m = 0; m < 2; m++)
                    mma_f16(acc[m][t][0], acc[m][t][1], acc[m][t][2], acc[m][t][3],
                            a[m][0], a[m][1], a[m][2], a[m][3], b.x, b.y);
            }
        }
    }
    BARP(1 + p);   // pair's reads of X0 complete before in-place X1 store
    {
        #pragma unroll
        for (int m = 0; m < 2; m++) {
            __half2 mk0 = __float2half2_rn(sM[p * N_ + m * 16 + r0]);
            __half2 mk1 = __float2half2_rn(sM[p * N_ + m * 16 + r0 + 8]);
            #pragma unroll
            for (int t = 0; t < 4; t++) {
                int wc = w * 16 + t * 4 + c0;
                int nb = (m * 16 + r0) * SAWH;
                sAp[nb + wc]            = h2bits(__hmul2(__hmax2(
                    __floats2half2_rn(acc[m][t][0], acc[m][t][1]), hz), mk0));
                sAp[nb + 8 * SAWH + wc] = h2bits(__hmul2(__hmax2(
                    __floats2half2_rn(acc[m][t][2], acc[m][t][3]), hz), mk1));
            }
        }
    }
    BARP(1 + p);

    // ---------------- stage 3: relu(X1 @ W2 + b2') * mask -> pool (regs only) ----------------
    {
        #pragma unroll
        for (int t = 0; t < 4; t++) {
            int hc = w * 32 + t * 8 + c0 * 2;
            float v0 = g_b2v[hc], v1 = g_b2v[hc + 1];
            #pragma unroll
            for (int m = 0; m < 2; m++) {
                acc[m][t][0] = v0; acc[m][t][1] = v1;
                acc[m][t][2] = v0; acc[m][t][3] = v1;
            }
        }
        const uint32_t* Wf = g_W2h + w * 1024;
        #pragma unroll
        for (int kt = 0; kt < 4; kt++) {
            uint32_t a[2][4];
            #pragma unroll
            for (int m = 0; m < 2; m++) {
                int base = (m * 16 + r0) * SAWH + kt * 8 + c0;
                a[m][0] = sAp[base];
                a[m][1] = sAp[base + 8 * SAWH];
                a[m][2] = sAp[base + 4];
                a[m][3] = sAp[base + 8 * SAWH + 4];
            }
            #pragma unroll
            for (int t = 0; t < 4; t++) {
                uint2 b = *(const uint2*)(Wf + ((kt * 4 + t) * 32 + lane) * 2);
                #pragma unroll
                for (int m = 0; m < 2; m++)
                    mma_f16(acc[m][t][0], acc[m][t][1], acc[m][t][2], acc[m][t][3],
                            a[m][0], a[m][1], a[m][2], a[m][3], b.x, b.y);
            }
        }
        // epilogue: relu*mask -> pool via half2 + shfl (no X2 store)
        uint32_t pm[4] = {0, 0, 0, 0};
        #pragma unroll
        for (int m = 0; m < 2; m++) {
            __half2 mk0 = __float2half2_rn(sM[p * N_ + m * 16 + r0]);
            __half2 mk1 = __float2half2_rn(sM[p * N_ + m * 16 + r0 + 8]);
            #pragma unroll
            for (int t = 0; t < 4; t++) {
                __half2 a01 = __hmul2(__hmax2(__floats2half2_rn(acc[m][t][0], acc[m][t][1]), hz), mk0);
                __half2 a23 = __hmul2(__hmax2(__floats2half2_rn(acc[m][t][2], acc[m][t][3]), hz), mk1);
                pm[t] = h2bits(__hmax2(bits2h(pm[t]), __hmax2(a01, a23)));
            }
        }
        #pragma unroll
        for (int s = 4; s < 32; s <<= 1) {
            #pragma unroll
            for (int t = 0; t < 4; t++)
                pm[t] = h2bits(__hmax2(bits2h(pm[t]),
                                       bits2h(__shfl_xor_sync(0xFFFFFFFFu, pm[t], s))));
        }
        if (r0 == 0) {
            #pragma unroll
            for (int t = 0; t < 4; t++)
                sPool3h[p * SVH + w * 16 + t * 4 + c0] = pm[t];
        }
    }
    __syncthreads();

    // ---------------- head part 1: H4 = relu(pooled3 @ W3 + b3)  (fp16, M=4) ----------------
    {
        const int tw = wid >> 2, tt4 = wid & 3;
        const int hc = wid * 8 + c0 * 2;
        float d0 = b3[hc], d1 = b3[hc + 1], d2 = 0.0f, d3 = 0.0f;
        #pragma unroll
        for (int kt = 0; kt < 4; kt++) {
            uint32_t a0 = 0, a2 = 0;
            if (r0 < 4) {
                a0 = sPool3h[r0 * SVH + kt * 8 + c0];
                a2 = sPool3h[r0 * SVH + kt * 8 + 4 + c0];
            }
            uint2 b = *(const uint2*)(g_W3h + (((tw * 4 + kt) * 4 + tt4) * 32 + lane) * 2);
            mma_f16(d0, d1, d2, d3, a0, 0u, a2, 0u, b.x, b.y);
        }
        if (r0 < 4)
            sH4h[r0 * SVH + wid * 4 + c0] = packh2(fmaxf(d0, 0.0f), fmaxf(d1, 0.0f));
    }
    __syncthreads();

    // ---------------- head part 2: out = (H4 @ W4 + b4) * anyvalid  (fp16, M=4, N=128) ----------------
    {
        const int tt0 = wid * 2;
        float e0[2], e1[2], e2[2], e3[2];
        #pragma unroll
        for (int j = 0; j < 2; j++) {
            int o = (tt0 + j) * 8 + c0 * 2;
            e0[j] = b4[o]; e1[j] = b4[o + 1]; e2[j] = 0.0f; e3[j] = 0.0f;
        }
        #pragma unroll
        for (int kt = 0; kt < 4; kt++) {
            uint32_t a0 = 0, a2 = 0;
            if (r0 < 4) {
                a0 = sH4h[r0 * SVH + kt * 8 + c0];
                a2 = sH4h[r0 * SVH + kt * 8 + 4 + c0];
            }
            #pragma unroll
            for (int j = 0; j < 2; j++) {
                uint2 b = *(const uint2*)(g_W4h + ((kt * 16 + tt0 + j) * 32 + lane) * 2);
                mma_f16(e0[j], e1[j], e2[j], e3[j], a0, 0u, a2, 0u, b.x, b.y);
            }
        }
        if (r0 < 4) {
            float vf = sValid[r0] ? 1.0f : 0.0f;
            #pragma unroll
            for (int j = 0; j < 2; j++) {
                int o = (tt0 + j) * 8 + c0 * 2;
                sOut[r0 * 132 + o]     = e0[j] * vf;
                sOut[r0 * 132 + o + 1] = e1[j] * vf;
            }
        }
    }
    __syncthreads();

    // ---------------- coalesced store ----------------
    if (tid < 128) {
        int pp = tid >> 5, j = tid & 31;
        int opid = blockIdx.x * 4 + pp;
        if (opid < npoly) {
            float4 v = *(const float4*)(sOut + pp * 132 + j * 4);
            *(float4*)(out + (size_t)opid * OUT_ + j * 4) = v;
        }
    }
}

// ============================================================
// Launch
// ============================================================
extern "C" void kernel_launch(void* const* d_in, const int* in_sizes, int n_in,
                              void* d_out, int out_size)
{
    const float* poly = (const float*)d_in[0];
    const float* Wpre = (const float*)d_in[1];
    const float* g0   = (const float*)d_in[2];
    const float* b0   = (const float*)d_in[3];
    const float* m0   = (const float*)d_in[4];
    const float* v0   = (const float*)d_in[5];
    const float* W1   = (const float*)d_in[6];
    const float* g1   = (const float*)d_in[7];
    const float* bb1  = (const float*)d_in[8];
    const float* m1   = (const float*)d_in[9];
    const float* v1   = (const float*)d_in[10];
    const float* W2   = (const float*)d_in[11];
    const float* g2   = (const float*)d_in[12];
    const float* bb2  = (const float*)d_in[13];
    const float* m2   = (const float*)d_in[14];
    const float* v2   = (const float*)d_in[15];
    const float* W3   = (const float*)d_in[16];
    const float* b3   = (const float*)d_in[17];
    const float* W4   = (const float*)d_in[18];
    const float* b4   = (const float*)d_in[19];
    const void*  mask = d_in[20];

    const int npoly = in_sizes[0] / (N_ * C_);

    fold_kernel<<<1, 256>>>(Wpre, g0, b0, m0, v0,
                            W1, g1, bb1, m1, v1,
                            W2, g2, bb2, m2, v2, W3, W4, mask);
    pnet_kernel<<<(npoly + 3) / 4, 256>>>(poly, mask, b3, b4, (float*)d_out, npoly);
}